// round 15
// baseline (speedup 1.0000x reference)
#include <cuda_runtime.h>
#include <cstddef>
#include <cstdint>

// ---------------- problem constants ----------------
#define TT   4
#define BB   8
#define CC   512
#define VV   1024
#define HID  2048
#define NTB  (TT*BB)              // 32
#define MAIN_ELEMS (TT*BB*CC*VV)  // 16,777,216
#define NBV  (BB*VV)              // 8192 (b,v) columns
#define NCOLT (NBV*4)             // 32768 (col,t) pairs

// ---------------- scratch ----------------
__device__ float g_xt[MAIN_ELEMS];      // x transposed [tb][v][c]
__device__ float g_xattn[MAIN_ELEMS];   // attn block output (residual for fc2)
__device__ float g_f2[MAIN_ELEMS];      // final sum, transposed [tb][v][c]
__device__ float g_dummy[MAIN_ELEMS];   // fallback v-out sink
__device__ float g_wqkv[CC*3*CC];       // [k][q512|k512|v512]
__device__ float g_wp [CC*CC];
__device__ float g_wf1[CC*HID];
__device__ float g_wf2[HID*CC];
// masks in [col][t][W] layout (col = b*1024+v) for CSR building
__device__ uint32_t g_mx [NCOLT*16];
__device__ uint32_t g_mm1[NCOLT*16];
__device__ uint32_t g_mh [NCOLT*64];
// masks in [tbv][16] layout for attention
__device__ uint32_t g_mq [NTB*VV*16];
__device__ uint32_t g_mk [NTB*VV*16];
__device__ uint32_t g_mv [NTB*VV*16];
__device__ uint32_t g_mpr[NTB*VV*16];
// CSR spike lists
__device__ uint16_t g_lstx[NCOLT*512 + 8];
__device__ uint16_t g_lstm[NCOLT*512 + 8];
__device__ int g_cntx[NCOLT];
__device__ int g_cntm[NCOLT];
__device__ float g_attn[128*4096];

// mask word from 2 spike bits per thread, 16-lane groups (channel = 2*(lane&15)+bit)
__device__ __forceinline__ void put_word2(uint32_t pr, int lane, uint32_t* dst)
{
    uint32_t gm = 0xFFFFu << (16 * (lane >> 4));
    uint32_t wd = __reduce_or_sync(gm, pr << ((lane & 15) * 2));
    if ((lane & 15) == 0) dst[lane >> 4] = wd;
}
// mask word from 4 spike bits per thread, 8-lane groups
__device__ __forceinline__ void put_word4(uint32_t nib, int lane, uint32_t* dst)
{
    uint32_t gm = 0xFFu << (8 * (lane >> 3));
    uint32_t wd = __reduce_or_sync(gm, nib << ((lane & 7) * 4));
    if ((lane & 7) == 0) dst[lane >> 3] = wd;
}

// ---------------- 32x32 tiled transpose ----------------
__global__ void tkern(const float* __restrict__ in, float* __restrict__ out,
                      int R, int Cn)
{
    __shared__ float t[32][33];
    size_t bs = (size_t)R * Cn * blockIdx.z;
    int r0 = blockIdx.y * 32, c0 = blockIdx.x * 32;
    int tx = threadIdx.x, ty = threadIdx.y;
#pragma unroll
    for (int j = 0; j < 4; j++)
        t[ty + 8 * j][tx] = in[bs + (size_t)(r0 + ty + 8 * j) * Cn + c0 + tx];
    __syncthreads();
#pragma unroll
    for (int j = 0; j < 4; j++)
        out[bs + (size_t)(c0 + ty + 8 * j) * R + r0 + tx] = t[tx][ty + 8 * j];
}

// ---------------- interleaved qkv weight transpose ----------------
__global__ void qkvw_kern(const float* __restrict__ qw, const float* __restrict__ kw,
                          const float* __restrict__ vw, float* __restrict__ wqkv)
{
    __shared__ float t[32][33];
    const float* src = (blockIdx.z == 0) ? qw : (blockIdx.z == 1) ? kw : vw;
    int m0 = blockIdx.y * 32, k0 = blockIdx.x * 32;
    int tx = threadIdx.x, ty = threadIdx.y;
#pragma unroll
    for (int j = 0; j < 4; j++)
        t[ty + 8 * j][tx] = src[(size_t)(m0 + ty + 8 * j) * CC + k0 + tx];
    __syncthreads();
#pragma unroll
    for (int j = 0; j < 4; j++)
        wqkv[(size_t)(k0 + ty + 8 * j) * 1536 + blockIdx.z * 512 + m0 + tx] = t[tx][ty + 8 * j];
}

// ---------------- LIF -> bitmask ([col][t][16] layout) ----------------
__global__ __launch_bounds__(256)
void lif2mask(const float* __restrict__ src, uint32_t* __restrict__ mout, float vth)
{
    int col = blockIdx.x;
    int b = col >> 10, v = col & 1023;
    int tid = threadIdx.x, wid = tid >> 5, lane = tid & 31;
    float v0 = 0.f, v1 = 0.f;
#pragma unroll
    for (int t = 0; t < 4; t++) {
        size_t ib = ((size_t)((t * 8 + b) * 1024 + v)) * 512;
        float2 xv = *(const float2*)(src + ib + 2 * tid);
        float h0 = v0 + (xv.x - v0) * 0.5f, h1 = v1 + (xv.y - v1) * 0.5f;
        uint32_t s0 = (h0 >= vth), s1 = (h1 >= vth);
        v0 = s0 ? 0.f : h0; v1 = s1 ? 0.f : h1;
        put_word2(s0 | (s1 << 1), lane, mout + (size_t)col * 64 + t * 16 + 2 * wid);
    }
}

// ---------------- bitmask (16 words) -> CSR index list; 1 warp per colt ----------------
__global__ __launch_bounds__(256)
void mask2csr(const uint32_t* __restrict__ m, int* __restrict__ cnt,
              uint16_t* __restrict__ lst)
{
    int colt = blockIdx.x * 8 + (threadIdx.x >> 5);
    int lane = threadIdx.x & 31;
    uint32_t w = (lane < 16) ? m[(size_t)colt * 16 + lane] : 0u;
    int c = __popc(w);
    int off = c;
#pragma unroll
    for (int d = 1; d < 32; d <<= 1) {
        int o = __shfl_up_sync(0xffffffffu, off, d);
        if (lane >= d) off += o;
    }
    int total = __shfl_sync(0xffffffffu, off, 31);
    int base = off - c;
    uint16_t* L = lst + (size_t)colt * 512;
    while (w) {
        int b = __ffs(w) - 1; w &= w - 1;
        L[base++] = (uint16_t)(lane * 32 + b);
    }
    if (lane == 0) cnt[colt] = total;
}

// ---------------- L1-tiled sparse gather: qkv ----------------
// grid (32 col-groups of 256, 24 m-tiles), 1024 threads = 32 warps.
// Warp owns 8 columns sequentially; thread owns 2 channels of its 64-ch tile.
// Weight tile working set = 512 rows x 256B (2 lines/row) = 128KB -> L1-resident.
__global__ __launch_bounds__(1024)
void qkv_tiled(const float* __restrict__ wqkv,
               const int* __restrict__ cnt, const uint16_t* __restrict__ lst,
               uint32_t* __restrict__ mq, uint32_t* __restrict__ mk2,
               uint32_t* __restrict__ mv,
               float* __restrict__ vout, int write_v,
               const float* __restrict__ qs, const float* __restrict__ qb,
               const float* __restrict__ ks_, const float* __restrict__ kb,
               const float* __restrict__ vs, const float* __restrict__ vb)
{
    int cg = blockIdx.x;
    int mb = blockIdx.y;
    int part = mb >> 3, sub = mb & 7;
    int tid = threadIdx.x, wid = tid >> 5, lane = tid & 31;

    const float* sp = (part == 0) ? qs : (part == 1) ? ks_ : vs;
    const float* bp = (part == 0) ? qb : (part == 1) ? kb : vb;
    uint32_t* mo = (part == 0) ? mq : (part == 1) ? mk2 : mv;
    int c0 = sub * 64 + 2 * lane;
    float s0 = sp[c0], s1 = sp[c0 + 1];
    float b0 = bp[c0], b1 = bp[c0 + 1];
    const float* tbl = wqkv + part * 512 + sub * 64 + 2 * lane;

#pragma unroll 1
    for (int cj = 0; cj < 8; cj++) {
        int col = cg * 256 + wid * 8 + cj;
        int b_ = col >> 10, v_ = col & 1023;
        float mf0 = 0.f, mf1 = 0.f;
#pragma unroll 1
        for (int t = 0; t < 4; t++) {
            int colt = col * 4 + t;
            int n = cnt[colt];
            const uint16_t* L = lst + (size_t)colt * 512;
            float a0 = 0.f, a1 = 0.f;
            int i = 0;
            for (; i + 4 <= n; i += 4) {
                ushort4 I = *(const ushort4*)(L + i);
                float2 u0 = *(const float2*)(tbl + (int)I.x * 1536);
                float2 u1 = *(const float2*)(tbl + (int)I.y * 1536);
                float2 u2 = *(const float2*)(tbl + (int)I.z * 1536);
                float2 u3 = *(const float2*)(tbl + (int)I.w * 1536);
                a0 += u0.x; a1 += u0.y; a0 += u1.x; a1 += u1.y;
                a0 += u2.x; a1 += u2.y; a0 += u3.x; a1 += u3.y;
            }
            for (; i < n; i++) {
                float2 u0 = *(const float2*)(tbl + (int)L[i] * 1536);
                a0 += u0.x; a1 += u0.y;
            }
            float p, h;
            p = a0 * s0 + b0; h = mf0 + (p - mf0) * 0.5f;
            uint32_t ss0 = (h >= 1.f); mf0 = ss0 ? 0.f : h;
            p = a1 * s1 + b1; h = mf1 + (p - mf1) * 0.5f;
            uint32_t ss1 = (h >= 1.f); mf1 = ss1 ? 0.f : h;
            size_t col16 = ((size_t)((t * 8 + b_) * 1024 + v_)) * 16;
            put_word2(ss0 | (ss1 << 1), lane, mo + col16 + 2 * sub);
            if (part == 2 && write_v) {
                int tb = t * 8 + b_;
                float2 f = make_float2(ss0 ? 1.f : 0.f, ss1 ? 1.f : 0.f);
                *(float2*)(vout + ((size_t)(tb * 8 + sub) * 1024 + v_) * 64 + 2 * lane) = f;
            }
        }
    }
}

// ---------------- L1-tiled sparse gather: fc1 ----------------
// grid (32 col-groups, 32 m-tiles). pre = (a + f1b)*f1s + f1sb, LIF(1.0) -> mh
__global__ __launch_bounds__(1024)
void fc1_tiled(const float* __restrict__ wf1,
               const int* __restrict__ cnt, const uint16_t* __restrict__ lst,
               const float* __restrict__ f1b, const float* __restrict__ f1s,
               const float* __restrict__ f1sb,
               uint32_t* __restrict__ mh)
{
    int cg = blockIdx.x;
    int mb = blockIdx.y;
    int tid = threadIdx.x, wid = tid >> 5, lane = tid & 31;

    int c0 = mb * 64 + 2 * lane;
    float cb0 = f1b[c0], cb1 = f1b[c0 + 1];
    float s0 = f1s[c0], s1 = f1s[c0 + 1];
    float b0 = f1sb[c0], b1 = f1sb[c0 + 1];
    const float* tbl = wf1 + mb * 64 + 2 * lane;

#pragma unroll 1
    for (int cj = 0; cj < 8; cj++) {
        int col = cg * 256 + wid * 8 + cj;
        float mf0 = 0.f, mf1 = 0.f;
#pragma unroll 1
        for (int t = 0; t < 4; t++) {
            int colt = col * 4 + t;
            int n = cnt[colt];
            const uint16_t* L = lst + (size_t)colt * 512;
            float a0 = 0.f, a1 = 0.f;
            int i = 0;
            for (; i + 4 <= n; i += 4) {
                ushort4 I = *(const ushort4*)(L + i);
                float2 u0 = *(const float2*)(tbl + (int)I.x * 2048);
                float2 u1 = *(const float2*)(tbl + (int)I.y * 2048);
                float2 u2 = *(const float2*)(tbl + (int)I.z * 2048);
                float2 u3 = *(const float2*)(tbl + (int)I.w * 2048);
                a0 += u0.x; a1 += u0.y; a0 += u1.x; a1 += u1.y;
                a0 += u2.x; a1 += u2.y; a0 += u3.x; a1 += u3.y;
            }
            for (; i < n; i++) {
                float2 u0 = *(const float2*)(tbl + (int)L[i] * 2048);
                a0 += u0.x; a1 += u0.y;
            }
            float p, h;
            p = (a0 + cb0) * s0 + b0; h = mf0 + (p - mf0) * 0.5f;
            uint32_t ss0 = (h >= 1.f); mf0 = ss0 ? 0.f : h;
            p = (a1 + cb1) * s1 + b1; h = mf1 + (p - mf1) * 0.5f;
            uint32_t ss1 = (h >= 1.f); mf1 = ss1 ? 0.f : h;
            put_word2(ss0 | (ss1 << 1), lane, mh + (size_t)colt * 64 + 2 * mb);
        }
    }
}

// ---------------- attn phase 1: popcount K^T V ----------------
__global__ __launch_bounds__(256)
void attn1_kernel(const uint32_t* __restrict__ mkb, const uint32_t* __restrict__ mv,
                  float* __restrict__ attn)
{
    int idx = blockIdx.x;
    int h = idx & 7, b = (idx >> 3) & 7, n_ = idx >> 6;
    __shared__ uint32_t Kw[64][65];
    __shared__ uint32_t Vw[64][65];
    int tid = threadIdx.x, wid = tid >> 5, lane = tid & 31;

    for (int chunk = wid; chunk < 64; chunk += 8) {
        int t = (n_ << 1) + (chunk >> 5);
        int nn = (chunk & 31) * 32 + lane;
        size_t col16 = ((size_t)((t * 8 + b) * 1024 + nn)) * 16;
        uint32_t k0 = mkb[col16 + 2 * h], k1 = mkb[col16 + 2 * h + 1];
        uint32_t v0 = mv[col16 + 2 * h],  v1 = mv[col16 + 2 * h + 1];
#pragma unroll
        for (int d = 0; d < 32; d++) {
            uint32_t bk = __ballot_sync(0xffffffffu, (k0 >> d) & 1);
            uint32_t bv = __ballot_sync(0xffffffffu, (v0 >> d) & 1);
            if (lane == 0) { Kw[d][chunk] = bk; Vw[d][chunk] = bv; }
        }
#pragma unroll
        for (int d = 0; d < 32; d++) {
            uint32_t bk = __ballot_sync(0xffffffffu, (k1 >> d) & 1);
            uint32_t bv = __ballot_sync(0xffffffffu, (v1 >> d) & 1);
            if (lane == 0) { Kw[32 + d][chunk] = bk; Vw[32 + d][chunk] = bv; }
        }
    }
    __syncthreads();

    int d = tid >> 2, eg = tid & 3;
    int acc[16];
#pragma unroll
    for (int j = 0; j < 16; j++) acc[j] = 0;
#pragma unroll 4
    for (int w = 0; w < 64; w++) {
        uint32_t kw = Kw[d][w];
#pragma unroll
        for (int j = 0; j < 16; j++)
            acc[j] += __popc(kw & Vw[eg + 4 * j][w]);
    }
    float* dst = attn + (size_t)idx * 4096 + d * 64 + eg;
#pragma unroll
    for (int j = 0; j < 16; j++)
        dst[4 * j] = (float)acc[j] * (1.0f / 1024.0f);
}

// ---------------- attn phase 2 fused with attn-LIF: proj-input masks only ----------
__global__ __launch_bounds__(256)
void attn2mask(const uint32_t* __restrict__ mq, const float* __restrict__ attn,
               uint32_t* __restrict__ mpr)
{
    int vtile = blockIdx.x;
    int bh = blockIdx.y;
    int h = bh & 7, b = bh >> 3;
    __shared__ float Atn[2][64 * 65];
    int tid = threadIdx.x;
#pragma unroll
    for (int n_ = 0; n_ < 2; n_++) {
        const float* src = attn + (size_t)(n_ * 64 + b * 8 + h) * 4096;
        for (int i = tid; i < 4096; i += 256)
            Atn[n_][(i >> 6) * 65 + (i & 63)] = src[i];
    }
    __syncthreads();

    int vl = tid >> 2, eg = tid & 3;
    int v = vtile * 64 + vl;
    int e0 = eg * 16;

    float mem[16];
#pragma unroll
    for (int j = 0; j < 16; j++) mem[j] = 0.f;

#pragma unroll 1
    for (int t = 0; t < 4; t++) {
        const float* A = Atn[t >> 1];
        size_t col16 = ((size_t)((t * 8 + b) * 1024 + v)) * 16;
        uint32_t q0 = mq[col16 + 2 * h], q1 = mq[col16 + 2 * h + 1];
        float acc[16];
#pragma unroll
        for (int j = 0; j < 16; j++) acc[j] = 0.f;
        while (q0) {
            int d = __ffs(q0) - 1; q0 &= q0 - 1;
            const float* a = A + d * 65 + e0;
#pragma unroll
            for (int j = 0; j < 16; j++) acc[j] += a[j];
        }
        while (q1) {
            int d = __ffs(q1) - 1 + 32; q1 &= q1 - 1;
            const float* a = A + d * 65 + e0;
#pragma unroll
            for (int j = 0; j < 16; j++) acc[j] += a[j];
        }
        uint32_t bits = 0;
#pragma unroll
        for (int j = 0; j < 16; j++) {
            float hh = mem[j] + (acc[j] - mem[j]) * 0.5f;
            uint32_t s = (hh >= 0.5f);
            mem[j] = s ? 0.f : hh;
            bits |= s << j;
        }
        uint32_t u = bits << ((tid & 1) * 16);
        u |= __shfl_xor_sync(0xffffffffu, u, 1);
        if ((tid & 1) == 0)
            mpr[col16 + 2 * h + (eg >> 1)] = u;
    }
}

// ---------------- proj: mpr gather + BN + residual -> xattn floats + mm1 masks ------
__global__ __launch_bounds__(256)
void projk2(const uint32_t* __restrict__ mprG, const float* __restrict__ xt,
            const float* __restrict__ wp,
            const float* __restrict__ pwb, const float* __restrict__ ps,
            const float* __restrict__ psb,
            float* __restrict__ xattn, uint32_t* __restrict__ mm1)
{
    int col = blockIdx.x;
    int b = col >> 10, v = col & 1023;
    int tid = threadIdx.x, wid = tid >> 5, lane = tid & 31;
    __shared__ uint32_t prw[16];
    __shared__ uint16_t lst[512];
    __shared__ int base[17];

    float2 pwb2 = *(const float2*)(pwb + 2 * tid);
    float2 ps2  = *(const float2*)(ps + 2 * tid);
    float2 psb2 = *(const float2*)(psb + 2 * tid);
    float vx0 = 0.f, vx1 = 0.f;

#pragma unroll 1
    for (int t = 0; t < 4; t++) {
        size_t ib = ((size_t)((t * 8 + b) * 1024 + v)) * 512;
        size_t col16 = ((size_t)((t * 8 + b) * 1024 + v)) * 16;
        if (tid < 16) prw[tid] = mprG[col16 + tid];
        __syncthreads();
        if (tid == 0) {
            int s = 0;
#pragma unroll
            for (int w = 0; w < 16; w++) { base[w] = s; s += __popc(prw[w]); }
            base[16] = s;
        }
        __syncthreads();
        if (tid < 16) {
            uint32_t m = prw[tid];
            int off = base[tid];
            while (m) { int bi = __ffs(m) - 1; m &= m - 1; lst[off++] = (uint16_t)(tid * 32 + bi); }
        }
        __syncthreads();
        int n = base[16];
        float a0 = 0.f, a1 = 0.f;
        int i = 0;
        for (; i + 4 <= n; i += 4) {
            float2 u0 = *(const float2*)(wp + (size_t)lst[i] * 512 + 2 * tid);
            float2 u1 = *(const float2*)(wp + (size_t)lst[i + 1] * 512 + 2 * tid);
            float2 u2 = *(const float2*)(wp + (size_t)lst[i + 2] * 512 + 2 * tid);
            float2 u3 = *(const float2*)(wp + (size_t)lst[i + 3] * 512 + 2 * tid);
            a0 += u0.x; a1 += u0.y; a0 += u1.x; a1 += u1.y;
            a0 += u2.x; a1 += u2.y; a0 += u3.x; a1 += u3.y;
        }
        for (; i < n; i++) {
            float2 u0 = *(const float2*)(wp + (size_t)lst[i] * 512 + 2 * tid);
            a0 += u0.x; a1 += u0.y;
        }
        float2 xres = *(const float2*)(xt + ib + 2 * tid);
        float xa0 = (a0 + pwb2.x) * ps2.x + psb2.x + xres.x;
        float xa1 = (a1 + pwb2.y) * ps2.y + psb2.y + xres.y;
        *(float2*)(xattn + ib + 2 * tid) = make_float2(xa0, xa1);

        float h0 = vx0 + (xa0 - vx0) * 0.5f, h1 = vx1 + (xa1 - vx1) * 0.5f;
        uint32_t s0 = (h0 >= 1.f), s1 = (h1 >= 1.f);
        vx0 = s0 ? 0.f : h0; vx1 = s1 ? 0.f : h1;
        put_word2(s0 | (s1 << 1), lane, mm1 + (size_t)col * 64 + t * 16 + 2 * wid);
        __syncthreads();
    }
}

// ---------------- fc2: gather by hidden masks + BN + residual -> f2o ----------
__global__ __launch_bounds__(256)
void fc2k(const uint32_t* __restrict__ mh, const float* __restrict__ wf2,
          const float* __restrict__ f2b, const float* __restrict__ f2s,
          const float* __restrict__ f2sb,
          const float* __restrict__ xattn, float* __restrict__ f2o)
{
    int col = blockIdx.x;
    int b = col >> 10, v = col & 1023;
    int tid = threadIdx.x;
    __shared__ uint32_t msk[64];
    __shared__ uint16_t lst[2048];
    __shared__ int base[65];

    float2 f2b2 = *(const float2*)(f2b + 2 * tid);
    float2 f2s2 = *(const float2*)(f2s + 2 * tid);
    float2 f2q2 = *(const float2*)(f2sb + 2 * tid);

#pragma unroll 1
    for (int t = 0; t < 4; t++) {
        if (tid < 64) msk[tid] = mh[((size_t)col * 4 + t) * 64 + tid];
        __syncthreads();
        if (tid == 0) {
            int s = 0;
            for (int w = 0; w < 64; w++) { base[w] = s; s += __popc(msk[w]); }
            base[64] = s;
        }
        __syncthreads();
        if (tid < 64) {
            uint32_t m = msk[tid];
            int off = base[tid];
            while (m) { int bi = __ffs(m) - 1; m &= m - 1; lst[off++] = (uint16_t)(tid * 32 + bi); }
        }
        __syncthreads();
        int n = base[64];
        float f0 = 0.f, f1 = 0.f;
        int i = 0;
        for (; i + 4 <= n; i += 4) {
            float2 u0 = *(const float2*)(wf2 + (size_t)lst[i] * 512 + 2 * tid);
            float2 u1 = *(const float2*)(wf2 + (size_t)lst[i + 1] * 512 + 2 * tid);
            float2 u2 = *(const float2*)(wf2 + (size_t)lst[i + 2] * 512 + 2 * tid);
            float2 u3 = *(const float2*)(wf2 + (size_t)lst[i + 3] * 512 + 2 * tid);
            f0 += u0.x; f1 += u0.y; f0 += u1.x; f1 += u1.y;
            f0 += u2.x; f1 += u2.y; f0 += u3.x; f1 += u3.y;
        }
        for (; i < n; i++) {
            float2 u0 = *(const float2*)(wf2 + (size_t)lst[i] * 512 + 2 * tid);
            f0 += u0.x; f1 += u0.y;
        }
        size_t ib = ((size_t)((t * 8 + b) * 1024 + v)) * 512;
        float2 rx = *(const float2*)(xattn + ib + 2 * tid);
        float2 o;
        o.x = (f0 + f2b2.x) * f2s2.x + f2q2.x + rx.x;
        o.y = (f1 + f2b2.y) * f2s2.y + f2q2.y + rx.y;
        *(float2*)(f2o + ib + 2 * tid) = o;
        __syncthreads();
    }
}

// ---------------- host launcher ----------------
extern "C" void kernel_launch(void* const* d_in, const int* in_sizes, int n_in,
                              void* d_out, int out_size)
{
    const float* x    = (const float*)d_in[0];
    const float* qw   = (const float*)d_in[1];
    const float* qs   = (const float*)d_in[2];
    const float* qb   = (const float*)d_in[3];
    const float* kw   = (const float*)d_in[4];
    const float* ks_  = (const float*)d_in[5];
    const float* kb   = (const float*)d_in[6];
    const float* vw   = (const float*)d_in[7];
    const float* vs   = (const float*)d_in[8];
    const float* vb   = (const float*)d_in[9];
    const float* pw   = (const float*)d_in[10];
    const float* pwb  = (const float*)d_in[11];
    const float* ps   = (const float*)d_in[12];
    const float* psb  = (const float*)d_in[13];
    const float* f1w  = (const float*)d_in[14];
    const float* f1b  = (const float*)d_in[15];
    const float* f1s  = (const float*)d_in[16];
    const float* f1sb = (const float*)d_in[17];
    const float* f2w  = (const float*)d_in[18];
    const float* f2b  = (const float*)d_in[19];
    const float* f2s  = (const float*)d_in[20];
    const float* f2sb = (const float*)d_in[21];

    float *xt, *xattn, *f2o, *dummy, *wqkv, *wp, *wf1, *wf2, *attn;
    uint32_t *mx, *mq, *mkb, *mv, *mpr, *mm1, *mh;
    uint16_t *lstx, *lstm;
    int *cntx, *cntm;
    cudaGetSymbolAddress((void**)&xt,    g_xt);
    cudaGetSymbolAddress((void**)&xattn, g_xattn);
    cudaGetSymbolAddress((void**)&f2o,   g_f2);
    cudaGetSymbolAddress((void**)&dummy, g_dummy);
    cudaGetSymbolAddress((void**)&wqkv,  g_wqkv);
    cudaGetSymbolAddress((void**)&wp,    g_wp);
    cudaGetSymbolAddress((void**)&wf1,   g_wf1);
    cudaGetSymbolAddress((void**)&wf2,   g_wf2);
    cudaGetSymbolAddress((void**)&attn,  g_attn);
    cudaGetSymbolAddress((void**)&mx,    g_mx);
    cudaGetSymbolAddress((void**)&mq,    g_mq);
    cudaGetSymbolAddress((void**)&mkb,   g_mk);
    cudaGetSymbolAddress((void**)&mv,    g_mv);
    cudaGetSymbolAddress((void**)&mpr,   g_mpr);
    cudaGetSymbolAddress((void**)&mm1,   g_mm1);
    cudaGetSymbolAddress((void**)&mh,    g_mh);
    cudaGetSymbolAddress((void**)&lstx,  g_lstx);
    cudaGetSymbolAddress((void**)&lstm,  g_lstm);
    cudaGetSymbolAddress((void**)&cntx,  g_cntx);
    cudaGetSymbolAddress((void**)&cntm,  g_cntm);

    float* out = (float*)d_out;
    int write_v = (out_size >= 2 * MAIN_ELEMS);
    float* vout = write_v ? (out + MAIN_ELEMS) : dummy;

    dim3 tb32(32, 8);
    qkvw_kern<<<dim3(CC / 32, CC / 32, 3), tb32>>>(qw, kw, vw, wqkv);
    tkern<<<dim3(CC / 32, CC / 32, 1), tb32>>>(pw,  wp,  CC,  CC);
    tkern<<<dim3(CC / 32, HID / 32, 1), tb32>>>(f1w, wf1, HID, CC);
    tkern<<<dim3(HID / 32, CC / 32, 1), tb32>>>(f2w, wf2, CC,  HID);

    // x -> [tb][v][c]
    tkern<<<dim3(VV / 32, CC / 32, NTB), tb32>>>(x, xt, CC, VV);

    // shortcut LIF -> x masks -> CSR lists
    lif2mask<<<NBV, 256>>>(xt, mx, 1.0f);
    mask2csr<<<NCOLT / 8, 256>>>(mx, cntx, lstx);

    // qkv: L1-tiled sparse gather + BN + LIF -> masks (+ v float spikes)
    qkv_tiled<<<dim3(32, 24), 1024>>>(wqkv, cntx, lstx, mq, mkb, mv, vout, write_v,
                                      qs, qb, ks_, kb, vs, vb);

    // bit-domain attention; phase 2 fused with attn-LIF -> proj-input masks
    attn1_kernel<<<128, 256>>>(mkb, mv, attn);
    attn2mask<<<dim3(16, 64), 256>>>(mq, attn, mpr);

    // proj + residual -> xattn floats + m1 masks -> CSR lists
    projk2<<<NBV, 256>>>(mpr, xt, wp, pwb, ps, psb, xattn, mm1);
    mask2csr<<<NCOLT / 8, 256>>>(mm1, cntm, lstm);

    // fc1: L1-tiled sparse gather + BN + LIF -> hidden masks
    fc1_tiled<<<dim3(32, 32), 1024>>>(wf1, cntm, lstm, f1b, f1s, f1sb, mh);

    // fc2 + BN + residual(xattn) -> f2o (coalesced)
    fc2k<<<NBV, 256>>>(mh, wf2, f2b, f2s, f2sb, xattn, f2o);

    // main output: transpose back to (T,B,C,V)
    tkern<<<dim3(CC / 32, VV / 32, NTB), tb32>>>(f2o, out, VV, CC);
}

// round 16
// speedup vs baseline: 1.4943x; 1.4943x over previous
#include <cuda_runtime.h>
#include <cstddef>
#include <cstdint>

// ---------------- problem constants ----------------
#define TT   4
#define BB   8
#define CC   512
#define VV   1024
#define HID  2048
#define NTB  (TT*BB)              // 32
#define MAIN_ELEMS (TT*BB*CC*VV)  // 16,777,216
#define NBV  (BB*VV)              // 8192 (b,v) columns
#define NCOLT (NBV*4)             // 32768 (col,t) pairs

// ---------------- scratch ----------------
__device__ float g_xt[MAIN_ELEMS];      // x transposed [tb][v][c]
__device__ float g_xattn[MAIN_ELEMS];   // attn block output (residual for fc2)
__device__ float g_f2[MAIN_ELEMS];      // final sum, transposed [tb][v][c]
__device__ float g_dummy[MAIN_ELEMS];   // fallback v-out sink
__device__ float g_wqkv[CC*3*CC];       // [k][q512|k512|v512]
__device__ float g_wp [CC*CC];
__device__ float g_wf1[CC*HID];
__device__ float g_wf2[HID*CC];
// masks in [col][t][W] layout (col = b*1024+v) for CSR building
__device__ uint32_t g_mx [NCOLT*16];
__device__ uint32_t g_mm1[NCOLT*16];
__device__ uint32_t g_mh [NCOLT*64];
// masks in [tbv][16] layout for attention
__device__ uint32_t g_mq [NTB*VV*16];
__device__ uint32_t g_mk [NTB*VV*16];
__device__ uint32_t g_mv [NTB*VV*16];
__device__ uint32_t g_mpr[NTB*VV*16];
// CSR spike lists
__device__ uint16_t g_lstx[NCOLT*512 + 8];
__device__ uint16_t g_lstm[NCOLT*512 + 8];
__device__ int g_cntx[NCOLT];
__device__ int g_cntm[NCOLT];
__device__ float g_attn[128*4096];

// mask word from 2 spike bits per thread, 16-lane groups (channel = 2*(lane&15)+bit)
__device__ __forceinline__ void put_word2(uint32_t pr, int lane, uint32_t* dst)
{
    uint32_t gm = 0xFFFFu << (16 * (lane >> 4));
    uint32_t wd = __reduce_or_sync(gm, pr << ((lane & 15) * 2));
    if ((lane & 15) == 0) dst[lane >> 4] = wd;
}
// mask word from 4 spike bits per thread, 8-lane groups
__device__ __forceinline__ void put_word4(uint32_t nib, int lane, uint32_t* dst)
{
    uint32_t gm = 0xFFu << (8 * (lane >> 3));
    uint32_t wd = __reduce_or_sync(gm, nib << ((lane & 7) * 4));
    if ((lane & 7) == 0) dst[lane >> 3] = wd;
}

// ---------------- 32x32 tiled transpose ----------------
__global__ void tkern(const float* __restrict__ in, float* __restrict__ out,
                      int R, int Cn)
{
    __shared__ float t[32][33];
    size_t bs = (size_t)R * Cn * blockIdx.z;
    int r0 = blockIdx.y * 32, c0 = blockIdx.x * 32;
    int tx = threadIdx.x, ty = threadIdx.y;
#pragma unroll
    for (int j = 0; j < 4; j++)
        t[ty + 8 * j][tx] = in[bs + (size_t)(r0 + ty + 8 * j) * Cn + c0 + tx];
    __syncthreads();
#pragma unroll
    for (int j = 0; j < 4; j++)
        out[bs + (size_t)(c0 + ty + 8 * j) * R + r0 + tx] = t[tx][ty + 8 * j];
}

// ---------------- interleaved qkv weight transpose ----------------
__global__ void qkvw_kern(const float* __restrict__ qw, const float* __restrict__ kw,
                          const float* __restrict__ vw, float* __restrict__ wqkv)
{
    __shared__ float t[32][33];
    const float* src = (blockIdx.z == 0) ? qw : (blockIdx.z == 1) ? kw : vw;
    int m0 = blockIdx.y * 32, k0 = blockIdx.x * 32;
    int tx = threadIdx.x, ty = threadIdx.y;
#pragma unroll
    for (int j = 0; j < 4; j++)
        t[ty + 8 * j][tx] = src[(size_t)(m0 + ty + 8 * j) * CC + k0 + tx];
    __syncthreads();
#pragma unroll
    for (int j = 0; j < 4; j++)
        wqkv[(size_t)(k0 + ty + 8 * j) * 1536 + blockIdx.z * 512 + m0 + tx] = t[tx][ty + 8 * j];
}

// ---------------- LIF -> bitmask ([col][t][16] layout) ----------------
__global__ __launch_bounds__(256)
void lif2mask(const float* __restrict__ src, uint32_t* __restrict__ mout, float vth)
{
    int col = blockIdx.x;
    int b = col >> 10, v = col & 1023;
    int tid = threadIdx.x, wid = tid >> 5, lane = tid & 31;
    float v0 = 0.f, v1 = 0.f;
#pragma unroll
    for (int t = 0; t < 4; t++) {
        size_t ib = ((size_t)((t * 8 + b) * 1024 + v)) * 512;
        float2 xv = *(const float2*)(src + ib + 2 * tid);
        float h0 = v0 + (xv.x - v0) * 0.5f, h1 = v1 + (xv.y - v1) * 0.5f;
        uint32_t s0 = (h0 >= vth), s1 = (h1 >= vth);
        v0 = s0 ? 0.f : h0; v1 = s1 ? 0.f : h1;
        put_word2(s0 | (s1 << 1), lane, mout + (size_t)col * 64 + t * 16 + 2 * wid);
    }
}

// ---------------- bitmask (16 words) -> CSR index list; 1 warp per colt ----------------
__global__ __launch_bounds__(256)
void mask2csr(const uint32_t* __restrict__ m, int* __restrict__ cnt,
              uint16_t* __restrict__ lst)
{
    int colt = blockIdx.x * 8 + (threadIdx.x >> 5);
    int lane = threadIdx.x & 31;
    uint32_t w = (lane < 16) ? m[(size_t)colt * 16 + lane] : 0u;
    int c = __popc(w);
    int off = c;
#pragma unroll
    for (int d = 1; d < 32; d <<= 1) {
        int o = __shfl_up_sync(0xffffffffu, off, d);
        if (lane >= d) off += o;
    }
    int total = __shfl_sync(0xffffffffu, off, 31);
    int base = off - c;
    uint16_t* L = lst + (size_t)colt * 512;
    while (w) {
        int b = __ffs(w) - 1; w &= w - 1;
        L[base++] = (uint16_t)(lane * 32 + b);
    }
    if (lane == 0) cnt[colt] = total;
}

// ---------------- L1-tiled sparse gather: qkv ----------------
// grid (32 col-groups of 256, 24 m-tiles), 1024 threads = 32 warps.
// Warp owns 8 columns sequentially; thread owns 2 channels of its 64-ch tile.
// Weight tile working set = 512 rows x 256B (2 lines/row) = 128KB -> L1-resident.
__global__ __launch_bounds__(1024)
void qkv_tiled(const float* __restrict__ wqkv,
               const int* __restrict__ cnt, const uint16_t* __restrict__ lst,
               uint32_t* __restrict__ mq, uint32_t* __restrict__ mk2,
               uint32_t* __restrict__ mv,
               float* __restrict__ vout, int write_v,
               const float* __restrict__ qs, const float* __restrict__ qb,
               const float* __restrict__ ks_, const float* __restrict__ kb,
               const float* __restrict__ vs, const float* __restrict__ vb)
{
    int cg = blockIdx.x;
    int mb = blockIdx.y;
    int part = mb >> 3, sub = mb & 7;
    int tid = threadIdx.x, wid = tid >> 5, lane = tid & 31;

    const float* sp = (part == 0) ? qs : (part == 1) ? ks_ : vs;
    const float* bp = (part == 0) ? qb : (part == 1) ? kb : vb;
    uint32_t* mo = (part == 0) ? mq : (part == 1) ? mk2 : mv;
    int c0 = sub * 64 + 2 * lane;
    float s0 = sp[c0], s1 = sp[c0 + 1];
    float b0 = bp[c0], b1 = bp[c0 + 1];
    const float* tbl = wqkv + part * 512 + sub * 64 + 2 * lane;

#pragma unroll 1
    for (int cj = 0; cj < 8; cj++) {
        int col = cg * 256 + wid * 8 + cj;
        int b_ = col >> 10, v_ = col & 1023;
        float mf0 = 0.f, mf1 = 0.f;
#pragma unroll 1
        for (int t = 0; t < 4; t++) {
            int colt = col * 4 + t;
            int n = cnt[colt];
            const uint16_t* L = lst + (size_t)colt * 512;
            float a0 = 0.f, a1 = 0.f;
            int i = 0;
            for (; i + 4 <= n; i += 4) {
                ushort4 I = *(const ushort4*)(L + i);
                float2 u0 = *(const float2*)(tbl + (int)I.x * 1536);
                float2 u1 = *(const float2*)(tbl + (int)I.y * 1536);
                float2 u2 = *(const float2*)(tbl + (int)I.z * 1536);
                float2 u3 = *(const float2*)(tbl + (int)I.w * 1536);
                a0 += u0.x; a1 += u0.y; a0 += u1.x; a1 += u1.y;
                a0 += u2.x; a1 += u2.y; a0 += u3.x; a1 += u3.y;
            }
            for (; i < n; i++) {
                float2 u0 = *(const float2*)(tbl + (int)L[i] * 1536);
                a0 += u0.x; a1 += u0.y;
            }
            float p, h;
            p = a0 * s0 + b0; h = mf0 + (p - mf0) * 0.5f;
            uint32_t ss0 = (h >= 1.f); mf0 = ss0 ? 0.f : h;
            p = a1 * s1 + b1; h = mf1 + (p - mf1) * 0.5f;
            uint32_t ss1 = (h >= 1.f); mf1 = ss1 ? 0.f : h;
            size_t col16 = ((size_t)((t * 8 + b_) * 1024 + v_)) * 16;
            put_word2(ss0 | (ss1 << 1), lane, mo + col16 + 2 * sub);
            if (part == 2 && write_v) {
                int tb = t * 8 + b_;
                float2 f = make_float2(ss0 ? 1.f : 0.f, ss1 ? 1.f : 0.f);
                *(float2*)(vout + ((size_t)(tb * 8 + sub) * 1024 + v_) * 64 + 2 * lane) = f;
            }
        }
    }
}

// ---------------- L1-tiled sparse gather: fc1 ----------------
// grid (32 col-groups, 32 m-tiles). pre = (a + f1b)*f1s + f1sb, LIF(1.0) -> mh
__global__ __launch_bounds__(1024)
void fc1_tiled(const float* __restrict__ wf1,
               const int* __restrict__ cnt, const uint16_t* __restrict__ lst,
               const float* __restrict__ f1b, const float* __restrict__ f1s,
               const float* __restrict__ f1sb,
               uint32_t* __restrict__ mh)
{
    int cg = blockIdx.x;
    int mb = blockIdx.y;
    int tid = threadIdx.x, wid = tid >> 5, lane = tid & 31;

    int c0 = mb * 64 + 2 * lane;
    float cb0 = f1b[c0], cb1 = f1b[c0 + 1];
    float s0 = f1s[c0], s1 = f1s[c0 + 1];
    float b0 = f1sb[c0], b1 = f1sb[c0 + 1];
    const float* tbl = wf1 + mb * 64 + 2 * lane;

#pragma unroll 1
    for (int cj = 0; cj < 8; cj++) {
        int col = cg * 256 + wid * 8 + cj;
        float mf0 = 0.f, mf1 = 0.f;
#pragma unroll 1
        for (int t = 0; t < 4; t++) {
            int colt = col * 4 + t;
            int n = cnt[colt];
            const uint16_t* L = lst + (size_t)colt * 512;
            float a0 = 0.f, a1 = 0.f;
            int i = 0;
            for (; i + 4 <= n; i += 4) {
                ushort4 I = *(const ushort4*)(L + i);
                float2 u0 = *(const float2*)(tbl + (int)I.x * 2048);
                float2 u1 = *(const float2*)(tbl + (int)I.y * 2048);
                float2 u2 = *(const float2*)(tbl + (int)I.z * 2048);
                float2 u3 = *(const float2*)(tbl + (int)I.w * 2048);
                a0 += u0.x; a1 += u0.y; a0 += u1.x; a1 += u1.y;
                a0 += u2.x; a1 += u2.y; a0 += u3.x; a1 += u3.y;
            }
            for (; i < n; i++) {
                float2 u0 = *(const float2*)(tbl + (int)L[i] * 2048);
                a0 += u0.x; a1 += u0.y;
            }
            float p, h;
            p = (a0 + cb0) * s0 + b0; h = mf0 + (p - mf0) * 0.5f;
            uint32_t ss0 = (h >= 1.f); mf0 = ss0 ? 0.f : h;
            p = (a1 + cb1) * s1 + b1; h = mf1 + (p - mf1) * 0.5f;
            uint32_t ss1 = (h >= 1.f); mf1 = ss1 ? 0.f : h;
            put_word2(ss0 | (ss1 << 1), lane, mh + (size_t)colt * 64 + 2 * mb);
        }
    }
}

// ---------------- attn phase 1: popcount K^T V ----------------
__global__ __launch_bounds__(256)
void attn1_kernel(const uint32_t* __restrict__ mkb, const uint32_t* __restrict__ mv,
                  float* __restrict__ attn)
{
    int idx = blockIdx.x;
    int h = idx & 7, b = (idx >> 3) & 7, n_ = idx >> 6;
    __shared__ uint32_t Kw[64][65];
    __shared__ uint32_t Vw[64][65];
    int tid = threadIdx.x, wid = tid >> 5, lane = tid & 31;

    for (int chunk = wid; chunk < 64; chunk += 8) {
        int t = (n_ << 1) + (chunk >> 5);
        int nn = (chunk & 31) * 32 + lane;
        size_t col16 = ((size_t)((t * 8 + b) * 1024 + nn)) * 16;
        uint32_t k0 = mkb[col16 + 2 * h], k1 = mkb[col16 + 2 * h + 1];
        uint32_t v0 = mv[col16 + 2 * h],  v1 = mv[col16 + 2 * h + 1];
#pragma unroll
        for (int d = 0; d < 32; d++) {
            uint32_t bk = __ballot_sync(0xffffffffu, (k0 >> d) & 1);
            uint32_t bv = __ballot_sync(0xffffffffu, (v0 >> d) & 1);
            if (lane == 0) { Kw[d][chunk] = bk; Vw[d][chunk] = bv; }
        }
#pragma unroll
        for (int d = 0; d < 32; d++) {
            uint32_t bk = __ballot_sync(0xffffffffu, (k1 >> d) & 1);
            uint32_t bv = __ballot_sync(0xffffffffu, (v1 >> d) & 1);
            if (lane == 0) { Kw[32 + d][chunk] = bk; Vw[32 + d][chunk] = bv; }
        }
    }
    __syncthreads();

    int d = tid >> 2, eg = tid & 3;
    int acc[16];
#pragma unroll
    for (int j = 0; j < 16; j++) acc[j] = 0;
#pragma unroll 4
    for (int w = 0; w < 64; w++) {
        uint32_t kw = Kw[d][w];
#pragma unroll
        for (int j = 0; j < 16; j++)
            acc[j] += __popc(kw & Vw[eg + 4 * j][w]);
    }
    float* dst = attn + (size_t)idx * 4096 + d * 64 + eg;
#pragma unroll
    for (int j = 0; j < 16; j++)
        dst[4 * j] = (float)acc[j] * (1.0f / 1024.0f);
}

// ---------------- attn phase 2 fused with attn-LIF: proj-input masks only ----------
__global__ __launch_bounds__(256)
void attn2mask(const uint32_t* __restrict__ mq, const float* __restrict__ attn,
               uint32_t* __restrict__ mpr)
{
    int vtile = blockIdx.x;
    int bh = blockIdx.y;
    int h = bh & 7, b = bh >> 3;
    __shared__ float Atn[2][64 * 65];
    int tid = threadIdx.x;
#pragma unroll
    for (int n_ = 0; n_ < 2; n_++) {
        const float* src = attn + (size_t)(n_ * 64 + b * 8 + h) * 4096;
        for (int i = tid; i < 4096; i += 256)
            Atn[n_][(i >> 6) * 65 + (i & 63)] = src[i];
    }
    __syncthreads();

    int vl = tid >> 2, eg = tid & 3;
    int v = vtile * 64 + vl;
    int e0 = eg * 16;

    float mem[16];
#pragma unroll
    for (int j = 0; j < 16; j++) mem[j] = 0.f;

#pragma unroll 1
    for (int t = 0; t < 4; t++) {
        const float* A = Atn[t >> 1];
        size_t col16 = ((size_t)((t * 8 + b) * 1024 + v)) * 16;
        uint32_t q0 = mq[col16 + 2 * h], q1 = mq[col16 + 2 * h + 1];
        float acc[16];
#pragma unroll
        for (int j = 0; j < 16; j++) acc[j] = 0.f;
        while (q0) {
            int d = __ffs(q0) - 1; q0 &= q0 - 1;
            const float* a = A + d * 65 + e0;
#pragma unroll
            for (int j = 0; j < 16; j++) acc[j] += a[j];
        }
        while (q1) {
            int d = __ffs(q1) - 1 + 32; q1 &= q1 - 1;
            const float* a = A + d * 65 + e0;
#pragma unroll
            for (int j = 0; j < 16; j++) acc[j] += a[j];
        }
        uint32_t bits = 0;
#pragma unroll
        for (int j = 0; j < 16; j++) {
            float hh = mem[j] + (acc[j] - mem[j]) * 0.5f;
            uint32_t s = (hh >= 0.5f);
            mem[j] = s ? 0.f : hh;
            bits |= s << j;
        }
        uint32_t u = bits << ((tid & 1) * 16);
        u |= __shfl_xor_sync(0xffffffffu, u, 1);
        if ((tid & 1) == 0)
            mpr[col16 + 2 * h + (eg >> 1)] = u;
    }
}

// ---------------- proj: mpr gather + BN + residual -> xattn floats + mm1 masks ------
__global__ __launch_bounds__(256)
void projk2(const uint32_t* __restrict__ mprG, const float* __restrict__ xt,
            const float* __restrict__ wp,
            const float* __restrict__ pwb, const float* __restrict__ ps,
            const float* __restrict__ psb,
            float* __restrict__ xattn, uint32_t* __restrict__ mm1)
{
    int col = blockIdx.x;
    int b = col >> 10, v = col & 1023;
    int tid = threadIdx.x, wid = tid >> 5, lane = tid & 31;
    __shared__ uint32_t prw[16];
    __shared__ uint16_t lst[512];
    __shared__ int base[17];

    float2 pwb2 = *(const float2*)(pwb + 2 * tid);
    float2 ps2  = *(const float2*)(ps + 2 * tid);
    float2 psb2 = *(const float2*)(psb + 2 * tid);
    float vx0 = 0.f, vx1 = 0.f;

#pragma unroll 1
    for (int t = 0; t < 4; t++) {
        size_t ib = ((size_t)((t * 8 + b) * 1024 + v)) * 512;
        size_t col16 = ((size_t)((t * 8 + b) * 1024 + v)) * 16;
        if (tid < 16) prw[tid] = mprG[col16 + tid];
        __syncthreads();
        if (tid == 0) {
            int s = 0;
#pragma unroll
            for (int w = 0; w < 16; w++) { base[w] = s; s += __popc(prw[w]); }
            base[16] = s;
        }
        __syncthreads();
        if (tid < 16) {
            uint32_t m = prw[tid];
            int off = base[tid];
            while (m) { int bi = __ffs(m) - 1; m &= m - 1; lst[off++] = (uint16_t)(tid * 32 + bi); }
        }
        __syncthreads();
        int n = base[16];
        float a0 = 0.f, a1 = 0.f;
        int i = 0;
        for (; i + 4 <= n; i += 4) {
            float2 u0 = *(const float2*)(wp + (size_t)lst[i] * 512 + 2 * tid);
            float2 u1 = *(const float2*)(wp + (size_t)lst[i + 1] * 512 + 2 * tid);
            float2 u2 = *(const float2*)(wp + (size_t)lst[i + 2] * 512 + 2 * tid);
            float2 u3 = *(const float2*)(wp + (size_t)lst[i + 3] * 512 + 2 * tid);
            a0 += u0.x; a1 += u0.y; a0 += u1.x; a1 += u1.y;
            a0 += u2.x; a1 += u2.y; a0 += u3.x; a1 += u3.y;
        }
        for (; i < n; i++) {
            float2 u0 = *(const float2*)(wp + (size_t)lst[i] * 512 + 2 * tid);
            a0 += u0.x; a1 += u0.y;
        }
        float2 xres = *(const float2*)(xt + ib + 2 * tid);
        float xa0 = (a0 + pwb2.x) * ps2.x + psb2.x + xres.x;
        float xa1 = (a1 + pwb2.y) * ps2.y + psb2.y + xres.y;
        *(float2*)(xattn + ib + 2 * tid) = make_float2(xa0, xa1);

        float h0 = vx0 + (xa0 - vx0) * 0.5f, h1 = vx1 + (xa1 - vx1) * 0.5f;
        uint32_t s0 = (h0 >= 1.f), s1 = (h1 >= 1.f);
        vx0 = s0 ? 0.f : h0; vx1 = s1 ? 0.f : h1;
        put_word2(s0 | (s1 << 1), lane, mm1 + (size_t)col * 64 + t * 16 + 2 * wid);
        __syncthreads();
    }
}

// ---------------- fc2: gather by hidden masks + BN + residual -> f2o ----------
__global__ __launch_bounds__(256)
void fc2k(const uint32_t* __restrict__ mh, const float* __restrict__ wf2,
          const float* __restrict__ f2b, const float* __restrict__ f2s,
          const float* __restrict__ f2sb,
          const float* __restrict__ xattn, float* __restrict__ f2o)
{
    int col = blockIdx.x;
    int b = col >> 10, v = col & 1023;
    int tid = threadIdx.x;
    __shared__ uint32_t msk[64];
    __shared__ uint16_t lst[2048];
    __shared__ int base[65];

    float2 f2b2 = *(const float2*)(f2b + 2 * tid);
    float2 f2s2 = *(const float2*)(f2s + 2 * tid);
    float2 f2q2 = *(const float2*)(f2sb + 2 * tid);

#pragma unroll 1
    for (int t = 0; t < 4; t++) {
        if (tid < 64) msk[tid] = mh[((size_t)col * 4 + t) * 64 + tid];
        __syncthreads();
        if (tid == 0) {
            int s = 0;
            for (int w = 0; w < 64; w++) { base[w] = s; s += __popc(msk[w]); }
            base[64] = s;
        }
        __syncthreads();
        if (tid < 64) {
            uint32_t m = msk[tid];
            int off = base[tid];
            while (m) { int bi = __ffs(m) - 1; m &= m - 1; lst[off++] = (uint16_t)(tid * 32 + bi); }
        }
        __syncthreads();
        int n = base[64];
        float f0 = 0.f, f1 = 0.f;
        int i = 0;
        for (; i + 4 <= n; i += 4) {
            float2 u0 = *(const float2*)(wf2 + (size_t)lst[i] * 512 + 2 * tid);
            float2 u1 = *(const float2*)(wf2 + (size_t)lst[i + 1] * 512 + 2 * tid);
            float2 u2 = *(const float2*)(wf2 + (size_t)lst[i + 2] * 512 + 2 * tid);
            float2 u3 = *(const float2*)(wf2 + (size_t)lst[i + 3] * 512 + 2 * tid);
            f0 += u0.x; f1 += u0.y; f0 += u1.x; f1 += u1.y;
            f0 += u2.x; f1 += u2.y; f0 += u3.x; f1 += u3.y;
        }
        for (; i < n; i++) {
            float2 u0 = *(const float2*)(wf2 + (size_t)lst[i] * 512 + 2 * tid);
            f0 += u0.x; f1 += u0.y;
        }
        size_t ib = ((size_t)((t * 8 + b) * 1024 + v)) * 512;
        float2 rx = *(const float2*)(xattn + ib + 2 * tid);
        float2 o;
        o.x = (f0 + f2b2.x) * f2s2.x + f2q2.x + rx.x;
        o.y = (f1 + f2b2.y) * f2s2.y + f2q2.y + rx.y;
        *(float2*)(f2o + ib + 2 * tid) = o;
        __syncthreads();
    }
}

// ---------------- host launcher ----------------
extern "C" void kernel_launch(void* const* d_in, const int* in_sizes, int n_in,
                              void* d_out, int out_size)
{
    const float* x    = (const float*)d_in[0];
    const float* qw   = (const float*)d_in[1];
    const float* qs   = (const float*)d_in[2];
    const float* qb   = (const float*)d_in[3];
    const float* kw   = (const float*)d_in[4];
    const float* ks_  = (const float*)d_in[5];
    const float* kb   = (const float*)d_in[6];
    const float* vw   = (const float*)d_in[7];
    const float* vs   = (const float*)d_in[8];
    const float* vb   = (const float*)d_in[9];
    const float* pw   = (const float*)d_in[10];
    const float* pwb  = (const float*)d_in[11];
    const float* ps   = (const float*)d_in[12];
    const float* psb  = (const float*)d_in[13];
    const float* f1w  = (const float*)d_in[14];
    const float* f1b  = (const float*)d_in[15];
    const float* f1s  = (const float*)d_in[16];
    const float* f1sb = (const float*)d_in[17];
    const float* f2w  = (const float*)d_in[18];
    const float* f2b  = (const float*)d_in[19];
    const float* f2s  = (const float*)d_in[20];
    const float* f2sb = (const float*)d_in[21];

    float *xt, *xattn, *f2o, *dummy, *wqkv, *wp, *wf1, *wf2, *attn;
    uint32_t *mx, *mq, *mkb, *mv, *mpr, *mm1, *mh;
    uint16_t *lstx, *lstm;
    int *cntx, *cntm;
    cudaGetSymbolAddress((void**)&xt,    g_xt);
    cudaGetSymbolAddress((void**)&xattn, g_xattn);
    cudaGetSymbolAddress((void**)&f2o,   g_f2);
    cudaGetSymbolAddress((void**)&dummy, g_dummy);
    cudaGetSymbolAddress((void**)&wqkv,  g_wqkv);
    cudaGetSymbolAddress((void**)&wp,    g_wp);
    cudaGetSymbolAddress((void**)&wf1,   g_wf1);
    cudaGetSymbolAddress((void**)&wf2,   g_wf2);
    cudaGetSymbolAddress((void**)&attn,  g_attn);
    cudaGetSymbolAddress((void**)&mx,    g_mx);
    cudaGetSymbolAddress((void**)&mq,    g_mq);
    cudaGetSymbolAddress((void**)&mkb,   g_mk);
    cudaGetSymbolAddress((void**)&mv,    g_mv);
    cudaGetSymbolAddress((void**)&mpr,   g_mpr);
    cudaGetSymbolAddress((void**)&mm1,   g_mm1);
    cudaGetSymbolAddress((void**)&mh,    g_mh);
    cudaGetSymbolAddress((void**)&lstx,  g_lstx);
    cudaGetSymbolAddress((void**)&lstm,  g_lstm);
    cudaGetSymbolAddress((void**)&cntx,  g_cntx);
    cudaGetSymbolAddress((void**)&cntm,  g_cntm);

    float* out = (float*)d_out;
    int write_v = (out_size >= 2 * MAIN_ELEMS);
    float* vout = write_v ? (out + MAIN_ELEMS) : dummy;

    dim3 tb32(32, 8);
    qkvw_kern<<<dim3(CC / 32, CC / 32, 3), tb32>>>(qw, kw, vw, wqkv);
    tkern<<<dim3(CC / 32, CC / 32, 1), tb32>>>(pw,  wp,  CC,  CC);
    tkern<<<dim3(CC / 32, HID / 32, 1), tb32>>>(f1w, wf1, HID, CC);
    tkern<<<dim3(HID / 32, CC / 32, 1), tb32>>>(f2w, wf2, CC,  HID);

    // x -> [tb][v][c]
    tkern<<<dim3(VV / 32, CC / 32, NTB), tb32>>>(x, xt, CC, VV);

    // shortcut LIF -> x masks -> CSR lists
    lif2mask<<<NBV, 256>>>(xt, mx, 1.0f);
    mask2csr<<<NCOLT / 8, 256>>>(mx, cntx, lstx);

    // qkv: L1-tiled sparse gather + BN + LIF -> masks (+ v float spikes)
    qkv_tiled<<<dim3(32, 24), 1024>>>(wqkv, cntx, lstx, mq, mkb, mv, vout, write_v,
                                      qs, qb, ks_, kb, vs, vb);

    // bit-domain attention; phase 2 fused with attn-LIF -> proj-input masks
    attn1_kernel<<<128, 256>>>(mkb, mv, attn);
    attn2mask<<<dim3(16, 64), 256>>>(mq, attn, mpr);

    // proj + residual -> xattn floats + m1 masks -> CSR lists
    projk2<<<NBV, 256>>>(mpr, xt, wp, pwb, ps, psb, xattn, mm1);
    mask2csr<<<NCOLT / 8, 256>>>(mm1, cntm, lstm);

    // fc1: L1-tiled sparse gather + BN + LIF -> hidden masks
    fc1_tiled<<<dim3(32, 32), 1024>>>(wf1, cntm, lstm, f1b, f1s, f1sb, mh);

    // fc2 + BN + residual(xattn) -> f2o (coalesced)
    fc2k<<<NBV, 256>>>(mh, wf2, f2b, f2s, f2sb, xattn, f2o);

    // main output: transpose back to (T,B,C,V)
    tkern<<<dim3(CC / 32, VV / 32, NTB), tb32>>>(f2o, out, VV, CC);
}

// round 17
// speedup vs baseline: 1.5002x; 1.0039x over previous
#include <cuda_runtime.h>
#include <cstddef>
#include <cstdint>

// ---------------- problem constants ----------------
#define TT   4
#define BB   8
#define CC   512
#define VV   1024
#define HID  2048
#define NTB  (TT*BB)              // 32
#define MAIN_ELEMS (TT*BB*CC*VV)  // 16,777,216
#define NBV  (BB*VV)              // 8192 (b,v) columns
#define NCOLT (NBV*4)             // 32768 (col,t) pairs

// ---------------- scratch ----------------
__device__ float g_xt[MAIN_ELEMS];      // x transposed [tb][v][c]
__device__ float g_xattn[MAIN_ELEMS];   // attn block output (residual for fc2)
__device__ float g_f2[MAIN_ELEMS];      // final sum, transposed [tb][v][c]
__device__ float g_dummy[MAIN_ELEMS];   // fallback v-out sink
__device__ float g_wqkv[CC*3*CC];       // [k][q512|k512|v512]
__device__ float g_wp [CC*CC];
__device__ float g_wf1[CC*HID];
__device__ float g_wf2[HID*CC];
// masks in [col][t][W] layout (col = b*1024+v) for CSR building
__device__ uint32_t g_mx [NCOLT*16];
__device__ uint32_t g_mm1[NCOLT*16];
__device__ uint32_t g_mh [NCOLT*64];
// masks in [tbv][16] layout for attention
__device__ uint32_t g_mq [NTB*VV*16];
__device__ uint32_t g_mk [NTB*VV*16];
__device__ uint32_t g_mv [NTB*VV*16];
__device__ uint32_t g_mpr[NTB*VV*16];
// CSR spike lists
__device__ uint16_t g_lstx[NCOLT*512 + 8];
__device__ uint16_t g_lstm[NCOLT*512 + 8];
__device__ int g_cntx[NCOLT];
__device__ int g_cntm[NCOLT];
__device__ float g_attn[128*4096];

// mask word from 2 spike bits per thread, 16-lane groups (channel = 2*(lane&15)+bit)
__device__ __forceinline__ void put_word2(uint32_t pr, int lane, uint32_t* dst)
{
    uint32_t gm = 0xFFFFu << (16 * (lane >> 4));
    uint32_t wd = __reduce_or_sync(gm, pr << ((lane & 15) * 2));
    if ((lane & 15) == 0) dst[lane >> 4] = wd;
}
// mask word from 4 spike bits per thread, 8-lane groups
__device__ __forceinline__ void put_word4(uint32_t nib, int lane, uint32_t* dst)
{
    uint32_t gm = 0xFFu << (8 * (lane >> 3));
    uint32_t wd = __reduce_or_sync(gm, nib << ((lane & 7) * 4));
    if ((lane & 7) == 0) dst[lane >> 3] = wd;
}

// ---------------- 32x32 tiled transpose ----------------
__global__ void tkern(const float* __restrict__ in, float* __restrict__ out,
                      int R, int Cn)
{
    __shared__ float t[32][33];
    size_t bs = (size_t)R * Cn * blockIdx.z;
    int r0 = blockIdx.y * 32, c0 = blockIdx.x * 32;
    int tx = threadIdx.x, ty = threadIdx.y;
#pragma unroll
    for (int j = 0; j < 4; j++)
        t[ty + 8 * j][tx] = in[bs + (size_t)(r0 + ty + 8 * j) * Cn + c0 + tx];
    __syncthreads();
#pragma unroll
    for (int j = 0; j < 4; j++)
        out[bs + (size_t)(c0 + ty + 8 * j) * R + r0 + tx] = t[tx][ty + 8 * j];
}

// ---------------- interleaved qkv weight transpose ----------------
__global__ void qkvw_kern(const float* __restrict__ qw, const float* __restrict__ kw,
                          const float* __restrict__ vw, float* __restrict__ wqkv)
{
    __shared__ float t[32][33];
    const float* src = (blockIdx.z == 0) ? qw : (blockIdx.z == 1) ? kw : vw;
    int m0 = blockIdx.y * 32, k0 = blockIdx.x * 32;
    int tx = threadIdx.x, ty = threadIdx.y;
#pragma unroll
    for (int j = 0; j < 4; j++)
        t[ty + 8 * j][tx] = src[(size_t)(m0 + ty + 8 * j) * CC + k0 + tx];
    __syncthreads();
#pragma unroll
    for (int j = 0; j < 4; j++)
        wqkv[(size_t)(k0 + ty + 8 * j) * 1536 + blockIdx.z * 512 + m0 + tx] = t[tx][ty + 8 * j];
}

// ---------------- LIF -> bitmask ([col][t][16] layout) ----------------
__global__ __launch_bounds__(256)
void lif2mask(const float* __restrict__ src, uint32_t* __restrict__ mout, float vth)
{
    int col = blockIdx.x;
    int b = col >> 10, v = col & 1023;
    int tid = threadIdx.x, wid = tid >> 5, lane = tid & 31;
    float v0 = 0.f, v1 = 0.f;
#pragma unroll
    for (int t = 0; t < 4; t++) {
        size_t ib = ((size_t)((t * 8 + b) * 1024 + v)) * 512;
        float2 xv = *(const float2*)(src + ib + 2 * tid);
        float h0 = v0 + (xv.x - v0) * 0.5f, h1 = v1 + (xv.y - v1) * 0.5f;
        uint32_t s0 = (h0 >= vth), s1 = (h1 >= vth);
        v0 = s0 ? 0.f : h0; v1 = s1 ? 0.f : h1;
        put_word2(s0 | (s1 << 1), lane, mout + (size_t)col * 64 + t * 16 + 2 * wid);
    }
}

// ---------------- bitmask (16 words) -> CSR index list; 1 warp per colt ----------------
__global__ __launch_bounds__(256)
void mask2csr(const uint32_t* __restrict__ m, int* __restrict__ cnt,
              uint16_t* __restrict__ lst)
{
    int colt = blockIdx.x * 8 + (threadIdx.x >> 5);
    int lane = threadIdx.x & 31;
    uint32_t w = (lane < 16) ? m[(size_t)colt * 16 + lane] : 0u;
    int c = __popc(w);
    int off = c;
#pragma unroll
    for (int d = 1; d < 32; d <<= 1) {
        int o = __shfl_up_sync(0xffffffffu, off, d);
        if (lane >= d) off += o;
    }
    int total = __shfl_sync(0xffffffffu, off, 31);
    int base = off - c;
    uint16_t* L = lst + (size_t)colt * 512;
    while (w) {
        int b = __ffs(w) - 1; w &= w - 1;
        L[base++] = (uint16_t)(lane * 32 + b);
    }
    if (lane == 0) cnt[colt] = total;
}

// ---------------- L1-tiled sparse gather: qkv ----------------
// grid (32 col-groups of 256, 24 m-tiles), 1024 threads = 32 warps.
// Warp owns 8 columns sequentially; thread owns 2 channels of its 64-ch tile.
// Weight tile working set = 512 rows x 256B (2 lines/row) = 128KB -> L1-resident.
__global__ __launch_bounds__(1024)
void qkv_tiled(const float* __restrict__ wqkv,
               const int* __restrict__ cnt, const uint16_t* __restrict__ lst,
               uint32_t* __restrict__ mq, uint32_t* __restrict__ mk2,
               uint32_t* __restrict__ mv,
               float* __restrict__ vout, int write_v,
               const float* __restrict__ qs, const float* __restrict__ qb,
               const float* __restrict__ ks_, const float* __restrict__ kb,
               const float* __restrict__ vs, const float* __restrict__ vb)
{
    int cg = blockIdx.x;
    int mb = blockIdx.y;
    int part = mb >> 3, sub = mb & 7;
    int tid = threadIdx.x, wid = tid >> 5, lane = tid & 31;

    const float* sp = (part == 0) ? qs : (part == 1) ? ks_ : vs;
    const float* bp = (part == 0) ? qb : (part == 1) ? kb : vb;
    uint32_t* mo = (part == 0) ? mq : (part == 1) ? mk2 : mv;
    int c0 = sub * 64 + 2 * lane;
    float s0 = sp[c0], s1 = sp[c0 + 1];
    float b0 = bp[c0], b1 = bp[c0 + 1];
    const float* tbl = wqkv + part * 512 + sub * 64 + 2 * lane;

#pragma unroll 1
    for (int cj = 0; cj < 8; cj++) {
        int col = cg * 256 + wid * 8 + cj;
        int b_ = col >> 10, v_ = col & 1023;
        float mf0 = 0.f, mf1 = 0.f;
#pragma unroll 1
        for (int t = 0; t < 4; t++) {
            int colt = col * 4 + t;
            int n = cnt[colt];
            const uint16_t* L = lst + (size_t)colt * 512;
            float a0 = 0.f, a1 = 0.f;
            int i = 0;
            for (; i + 4 <= n; i += 4) {
                ushort4 I = *(const ushort4*)(L + i);
                float2 u0 = *(const float2*)(tbl + (int)I.x * 1536);
                float2 u1 = *(const float2*)(tbl + (int)I.y * 1536);
                float2 u2 = *(const float2*)(tbl + (int)I.z * 1536);
                float2 u3 = *(const float2*)(tbl + (int)I.w * 1536);
                a0 += u0.x; a1 += u0.y; a0 += u1.x; a1 += u1.y;
                a0 += u2.x; a1 += u2.y; a0 += u3.x; a1 += u3.y;
            }
            for (; i < n; i++) {
                float2 u0 = *(const float2*)(tbl + (int)L[i] * 1536);
                a0 += u0.x; a1 += u0.y;
            }
            float p, h;
            p = a0 * s0 + b0; h = mf0 + (p - mf0) * 0.5f;
            uint32_t ss0 = (h >= 1.f); mf0 = ss0 ? 0.f : h;
            p = a1 * s1 + b1; h = mf1 + (p - mf1) * 0.5f;
            uint32_t ss1 = (h >= 1.f); mf1 = ss1 ? 0.f : h;
            size_t col16 = ((size_t)((t * 8 + b_) * 1024 + v_)) * 16;
            put_word2(ss0 | (ss1 << 1), lane, mo + col16 + 2 * sub);
            if (part == 2 && write_v) {
                int tb = t * 8 + b_;
                float2 f = make_float2(ss0 ? 1.f : 0.f, ss1 ? 1.f : 0.f);
                *(float2*)(vout + ((size_t)(tb * 8 + sub) * 1024 + v_) * 64 + 2 * lane) = f;
            }
        }
    }
}

// ---------------- L1-tiled sparse gather: fc1 ----------------
// grid (32 col-groups, 32 m-tiles). pre = (a + f1b)*f1s + f1sb, LIF(1.0) -> mh
__global__ __launch_bounds__(1024)
void fc1_tiled(const float* __restrict__ wf1,
               const int* __restrict__ cnt, const uint16_t* __restrict__ lst,
               const float* __restrict__ f1b, const float* __restrict__ f1s,
               const float* __restrict__ f1sb,
               uint32_t* __restrict__ mh)
{
    int cg = blockIdx.x;
    int mb = blockIdx.y;
    int tid = threadIdx.x, wid = tid >> 5, lane = tid & 31;

    int c0 = mb * 64 + 2 * lane;
    float cb0 = f1b[c0], cb1 = f1b[c0 + 1];
    float s0 = f1s[c0], s1 = f1s[c0 + 1];
    float b0 = f1sb[c0], b1 = f1sb[c0 + 1];
    const float* tbl = wf1 + mb * 64 + 2 * lane;

#pragma unroll 1
    for (int cj = 0; cj < 8; cj++) {
        int col = cg * 256 + wid * 8 + cj;
        float mf0 = 0.f, mf1 = 0.f;
#pragma unroll 1
        for (int t = 0; t < 4; t++) {
            int colt = col * 4 + t;
            int n = cnt[colt];
            const uint16_t* L = lst + (size_t)colt * 512;
            float a0 = 0.f, a1 = 0.f;
            int i = 0;
            for (; i + 4 <= n; i += 4) {
                ushort4 I = *(const ushort4*)(L + i);
                float2 u0 = *(const float2*)(tbl + (int)I.x * 2048);
                float2 u1 = *(const float2*)(tbl + (int)I.y * 2048);
                float2 u2 = *(const float2*)(tbl + (int)I.z * 2048);
                float2 u3 = *(const float2*)(tbl + (int)I.w * 2048);
                a0 += u0.x; a1 += u0.y; a0 += u1.x; a1 += u1.y;
                a0 += u2.x; a1 += u2.y; a0 += u3.x; a1 += u3.y;
            }
            for (; i < n; i++) {
                float2 u0 = *(const float2*)(tbl + (int)L[i] * 2048);
                a0 += u0.x; a1 += u0.y;
            }
            float p, h;
            p = (a0 + cb0) * s0 + b0; h = mf0 + (p - mf0) * 0.5f;
            uint32_t ss0 = (h >= 1.f); mf0 = ss0 ? 0.f : h;
            p = (a1 + cb1) * s1 + b1; h = mf1 + (p - mf1) * 0.5f;
            uint32_t ss1 = (h >= 1.f); mf1 = ss1 ? 0.f : h;
            put_word2(ss0 | (ss1 << 1), lane, mh + (size_t)colt * 64 + 2 * mb);
        }
    }
}

// ---------------- attn phase 1: popcount K^T V ----------------
__global__ __launch_bounds__(256)
void attn1_kernel(const uint32_t* __restrict__ mkb, const uint32_t* __restrict__ mv,
                  float* __restrict__ attn)
{
    int idx = blockIdx.x;
    int h = idx & 7, b = (idx >> 3) & 7, n_ = idx >> 6;
    __shared__ uint32_t Kw[64][65];
    __shared__ uint32_t Vw[64][65];
    int tid = threadIdx.x, wid = tid >> 5, lane = tid & 31;

    for (int chunk = wid; chunk < 64; chunk += 8) {
        int t = (n_ << 1) + (chunk >> 5);
        int nn = (chunk & 31) * 32 + lane;
        size_t col16 = ((size_t)((t * 8 + b) * 1024 + nn)) * 16;
        uint32_t k0 = mkb[col16 + 2 * h], k1 = mkb[col16 + 2 * h + 1];
        uint32_t v0 = mv[col16 + 2 * h],  v1 = mv[col16 + 2 * h + 1];
#pragma unroll
        for (int d = 0; d < 32; d++) {
            uint32_t bk = __ballot_sync(0xffffffffu, (k0 >> d) & 1);
            uint32_t bv = __ballot_sync(0xffffffffu, (v0 >> d) & 1);
            if (lane == 0) { Kw[d][chunk] = bk; Vw[d][chunk] = bv; }
        }
#pragma unroll
        for (int d = 0; d < 32; d++) {
            uint32_t bk = __ballot_sync(0xffffffffu, (k1 >> d) & 1);
            uint32_t bv = __ballot_sync(0xffffffffu, (v1 >> d) & 1);
            if (lane == 0) { Kw[32 + d][chunk] = bk; Vw[32 + d][chunk] = bv; }
        }
    }
    __syncthreads();

    int d = tid >> 2, eg = tid & 3;
    int acc[16];
#pragma unroll
    for (int j = 0; j < 16; j++) acc[j] = 0;
#pragma unroll 4
    for (int w = 0; w < 64; w++) {
        uint32_t kw = Kw[d][w];
#pragma unroll
        for (int j = 0; j < 16; j++)
            acc[j] += __popc(kw & Vw[eg + 4 * j][w]);
    }
    float* dst = attn + (size_t)idx * 4096 + d * 64 + eg;
#pragma unroll
    for (int j = 0; j < 16; j++)
        dst[4 * j] = (float)acc[j] * (1.0f / 1024.0f);
}

// ---------------- attn phase 2 fused with attn-LIF: proj-input masks only ----------
__global__ __launch_bounds__(256)
void attn2mask(const uint32_t* __restrict__ mq, const float* __restrict__ attn,
               uint32_t* __restrict__ mpr)
{
    int vtile = blockIdx.x;
    int bh = blockIdx.y;
    int h = bh & 7, b = bh >> 3;
    __shared__ float Atn[2][64 * 65];
    int tid = threadIdx.x;
#pragma unroll
    for (int n_ = 0; n_ < 2; n_++) {
        const float* src = attn + (size_t)(n_ * 64 + b * 8 + h) * 4096;
        for (int i = tid; i < 4096; i += 256)
            Atn[n_][(i >> 6) * 65 + (i & 63)] = src[i];
    }
    __syncthreads();

    int vl = tid >> 2, eg = tid & 3;
    int v = vtile * 64 + vl;
    int e0 = eg * 16;

    float mem[16];
#pragma unroll
    for (int j = 0; j < 16; j++) mem[j] = 0.f;

#pragma unroll 1
    for (int t = 0; t < 4; t++) {
        const float* A = Atn[t >> 1];
        size_t col16 = ((size_t)((t * 8 + b) * 1024 + v)) * 16;
        uint32_t q0 = mq[col16 + 2 * h], q1 = mq[col16 + 2 * h + 1];
        float acc[16];
#pragma unroll
        for (int j = 0; j < 16; j++) acc[j] = 0.f;
        while (q0) {
            int d = __ffs(q0) - 1; q0 &= q0 - 1;
            const float* a = A + d * 65 + e0;
#pragma unroll
            for (int j = 0; j < 16; j++) acc[j] += a[j];
        }
        while (q1) {
            int d = __ffs(q1) - 1 + 32; q1 &= q1 - 1;
            const float* a = A + d * 65 + e0;
#pragma unroll
            for (int j = 0; j < 16; j++) acc[j] += a[j];
        }
        uint32_t bits = 0;
#pragma unroll
        for (int j = 0; j < 16; j++) {
            float hh = mem[j] + (acc[j] - mem[j]) * 0.5f;
            uint32_t s = (hh >= 0.5f);
            mem[j] = s ? 0.f : hh;
            bits |= s << j;
        }
        uint32_t u = bits << ((tid & 1) * 16);
        u |= __shfl_xor_sync(0xffffffffu, u, 1);
        if ((tid & 1) == 0)
            mpr[col16 + 2 * h + (eg >> 1)] = u;
    }
}

// ---------------- proj: mpr gather + BN + residual -> xattn floats + mm1 masks ------
__global__ __launch_bounds__(256)
void projk2(const uint32_t* __restrict__ mprG, const float* __restrict__ xt,
            const float* __restrict__ wp,
            const float* __restrict__ pwb, const float* __restrict__ ps,
            const float* __restrict__ psb,
            float* __restrict__ xattn, uint32_t* __restrict__ mm1)
{
    int col = blockIdx.x;
    int b = col >> 10, v = col & 1023;
    int tid = threadIdx.x, wid = tid >> 5, lane = tid & 31;
    __shared__ uint32_t prw[16];
    __shared__ uint16_t lst[512];
    __shared__ int base[17];

    float2 pwb2 = *(const float2*)(pwb + 2 * tid);
    float2 ps2  = *(const float2*)(ps + 2 * tid);
    float2 psb2 = *(const float2*)(psb + 2 * tid);
    float vx0 = 0.f, vx1 = 0.f;

#pragma unroll 1
    for (int t = 0; t < 4; t++) {
        size_t ib = ((size_t)((t * 8 + b) * 1024 + v)) * 512;
        size_t col16 = ((size_t)((t * 8 + b) * 1024 + v)) * 16;
        if (tid < 16) prw[tid] = mprG[col16 + tid];
        __syncthreads();
        if (tid == 0) {
            int s = 0;
#pragma unroll
            for (int w = 0; w < 16; w++) { base[w] = s; s += __popc(prw[w]); }
            base[16] = s;
        }
        __syncthreads();
        if (tid < 16) {
            uint32_t m = prw[tid];
            int off = base[tid];
            while (m) { int bi = __ffs(m) - 1; m &= m - 1; lst[off++] = (uint16_t)(tid * 32 + bi); }
        }
        __syncthreads();
        int n = base[16];
        float a0 = 0.f, a1 = 0.f;
        int i = 0;
        for (; i + 4 <= n; i += 4) {
            float2 u0 = *(const float2*)(wp + (size_t)lst[i] * 512 + 2 * tid);
            float2 u1 = *(const float2*)(wp + (size_t)lst[i + 1] * 512 + 2 * tid);
            float2 u2 = *(const float2*)(wp + (size_t)lst[i + 2] * 512 + 2 * tid);
            float2 u3 = *(const float2*)(wp + (size_t)lst[i + 3] * 512 + 2 * tid);
            a0 += u0.x; a1 += u0.y; a0 += u1.x; a1 += u1.y;
            a0 += u2.x; a1 += u2.y; a0 += u3.x; a1 += u3.y;
        }
        for (; i < n; i++) {
            float2 u0 = *(const float2*)(wp + (size_t)lst[i] * 512 + 2 * tid);
            a0 += u0.x; a1 += u0.y;
        }
        float2 xres = *(const float2*)(xt + ib + 2 * tid);
        float xa0 = (a0 + pwb2.x) * ps2.x + psb2.x + xres.x;
        float xa1 = (a1 + pwb2.y) * ps2.y + psb2.y + xres.y;
        *(float2*)(xattn + ib + 2 * tid) = make_float2(xa0, xa1);

        float h0 = vx0 + (xa0 - vx0) * 0.5f, h1 = vx1 + (xa1 - vx1) * 0.5f;
        uint32_t s0 = (h0 >= 1.f), s1 = (h1 >= 1.f);
        vx0 = s0 ? 0.f : h0; vx1 = s1 ? 0.f : h1;
        put_word2(s0 | (s1 << 1), lane, mm1 + (size_t)col * 64 + t * 16 + 2 * wid);
        __syncthreads();
    }
}

// ---------------- fc2: gather by hidden masks + BN + residual -> f2o ----------
__global__ __launch_bounds__(256)
void fc2k(const uint32_t* __restrict__ mh, const float* __restrict__ wf2,
          const float* __restrict__ f2b, const float* __restrict__ f2s,
          const float* __restrict__ f2sb,
          const float* __restrict__ xattn, float* __restrict__ f2o)
{
    int col = blockIdx.x;
    int b = col >> 10, v = col & 1023;
    int tid = threadIdx.x;
    __shared__ uint32_t msk[64];
    __shared__ uint16_t lst[2048];
    __shared__ int base[65];

    float2 f2b2 = *(const float2*)(f2b + 2 * tid);
    float2 f2s2 = *(const float2*)(f2s + 2 * tid);
    float2 f2q2 = *(const float2*)(f2sb + 2 * tid);

#pragma unroll 1
    for (int t = 0; t < 4; t++) {
        if (tid < 64) msk[tid] = mh[((size_t)col * 4 + t) * 64 + tid];
        __syncthreads();
        if (tid == 0) {
            int s = 0;
            for (int w = 0; w < 64; w++) { base[w] = s; s += __popc(msk[w]); }
            base[64] = s;
        }
        __syncthreads();
        if (tid < 64) {
            uint32_t m = msk[tid];
            int off = base[tid];
            while (m) { int bi = __ffs(m) - 1; m &= m - 1; lst[off++] = (uint16_t)(tid * 32 + bi); }
        }
        __syncthreads();
        int n = base[64];
        float f0 = 0.f, f1 = 0.f;
        int i = 0;
        for (; i + 4 <= n; i += 4) {
            float2 u0 = *(const float2*)(wf2 + (size_t)lst[i] * 512 + 2 * tid);
            float2 u1 = *(const float2*)(wf2 + (size_t)lst[i + 1] * 512 + 2 * tid);
            float2 u2 = *(const float2*)(wf2 + (size_t)lst[i + 2] * 512 + 2 * tid);
            float2 u3 = *(const float2*)(wf2 + (size_t)lst[i + 3] * 512 + 2 * tid);
            f0 += u0.x; f1 += u0.y; f0 += u1.x; f1 += u1.y;
            f0 += u2.x; f1 += u2.y; f0 += u3.x; f1 += u3.y;
        }
        for (; i < n; i++) {
            float2 u0 = *(const float2*)(wf2 + (size_t)lst[i] * 512 + 2 * tid);
            f0 += u0.x; f1 += u0.y;
        }
        size_t ib = ((size_t)((t * 8 + b) * 1024 + v)) * 512;
        float2 rx = *(const float2*)(xattn + ib + 2 * tid);
        float2 o;
        o.x = (f0 + f2b2.x) * f2s2.x + f2q2.x + rx.x;
        o.y = (f1 + f2b2.y) * f2s2.y + f2q2.y + rx.y;
        *(float2*)(f2o + ib + 2 * tid) = o;
        __syncthreads();
    }
}

// ---------------- host launcher ----------------
extern "C" void kernel_launch(void* const* d_in, const int* in_sizes, int n_in,
                              void* d_out, int out_size)
{
    const float* x    = (const float*)d_in[0];
    const float* qw   = (const float*)d_in[1];
    const float* qs   = (const float*)d_in[2];
    const float* qb   = (const float*)d_in[3];
    const float* kw   = (const float*)d_in[4];
    const float* ks_  = (const float*)d_in[5];
    const float* kb   = (const float*)d_in[6];
    const float* vw   = (const float*)d_in[7];
    const float* vs   = (const float*)d_in[8];
    const float* vb   = (const float*)d_in[9];
    const float* pw   = (const float*)d_in[10];
    const float* pwb  = (const float*)d_in[11];
    const float* ps   = (const float*)d_in[12];
    const float* psb  = (const float*)d_in[13];
    const float* f1w  = (const float*)d_in[14];
    const float* f1b  = (const float*)d_in[15];
    const float* f1s  = (const float*)d_in[16];
    const float* f1sb = (const float*)d_in[17];
    const float* f2w  = (const float*)d_in[18];
    const float* f2b  = (const float*)d_in[19];
    const float* f2s  = (const float*)d_in[20];
    const float* f2sb = (const float*)d_in[21];

    float *xt, *xattn, *f2o, *dummy, *wqkv, *wp, *wf1, *wf2, *attn;
    uint32_t *mx, *mq, *mkb, *mv, *mpr, *mm1, *mh;
    uint16_t *lstx, *lstm;
    int *cntx, *cntm;
    cudaGetSymbolAddress((void**)&xt,    g_xt);
    cudaGetSymbolAddress((void**)&xattn, g_xattn);
    cudaGetSymbolAddress((void**)&f2o,   g_f2);
    cudaGetSymbolAddress((void**)&dummy, g_dummy);
    cudaGetSymbolAddress((void**)&wqkv,  g_wqkv);
    cudaGetSymbolAddress((void**)&wp,    g_wp);
    cudaGetSymbolAddress((void**)&wf1,   g_wf1);
    cudaGetSymbolAddress((void**)&wf2,   g_wf2);
    cudaGetSymbolAddress((void**)&attn,  g_attn);
    cudaGetSymbolAddress((void**)&mx,    g_mx);
    cudaGetSymbolAddress((void**)&mq,    g_mq);
    cudaGetSymbolAddress((void**)&mkb,   g_mk);
    cudaGetSymbolAddress((void**)&mv,    g_mv);
    cudaGetSymbolAddress((void**)&mpr,   g_mpr);
    cudaGetSymbolAddress((void**)&mm1,   g_mm1);
    cudaGetSymbolAddress((void**)&mh,    g_mh);
    cudaGetSymbolAddress((void**)&lstx,  g_lstx);
    cudaGetSymbolAddress((void**)&lstm,  g_lstm);
    cudaGetSymbolAddress((void**)&cntx,  g_cntx);
    cudaGetSymbolAddress((void**)&cntm,  g_cntm);

    float* out = (float*)d_out;
    int write_v = (out_size >= 2 * MAIN_ELEMS);
    float* vout = write_v ? (out + MAIN_ELEMS) : dummy;

    dim3 tb32(32, 8);
    qkvw_kern<<<dim3(CC / 32, CC / 32, 3), tb32>>>(qw, kw, vw, wqkv);
    tkern<<<dim3(CC / 32, CC / 32, 1), tb32>>>(pw,  wp,  CC,  CC);
    tkern<<<dim3(CC / 32, HID / 32, 1), tb32>>>(f1w, wf1, HID, CC);
    tkern<<<dim3(HID / 32, CC / 32, 1), tb32>>>(f2w, wf2, CC,  HID);

    // x -> [tb][v][c]
    tkern<<<dim3(VV / 32, CC / 32, NTB), tb32>>>(x, xt, CC, VV);

    // shortcut LIF -> x masks -> CSR lists
    lif2mask<<<NBV, 256>>>(xt, mx, 1.0f);
    mask2csr<<<NCOLT / 8, 256>>>(mx, cntx, lstx);

    // qkv: L1-tiled sparse gather + BN + LIF -> masks (+ v float spikes)
    qkv_tiled<<<dim3(32, 24), 1024>>>(wqkv, cntx, lstx, mq, mkb, mv, vout, write_v,
                                      qs, qb, ks_, kb, vs, vb);

    // bit-domain attention; phase 2 fused with attn-LIF -> proj-input masks
    attn1_kernel<<<128, 256>>>(mkb, mv, attn);
    attn2mask<<<dim3(16, 64), 256>>>(mq, attn, mpr);

    // proj + residual -> xattn floats + m1 masks -> CSR lists
    projk2<<<NBV, 256>>>(mpr, xt, wp, pwb, ps, psb, xattn, mm1);
    mask2csr<<<NCOLT / 8, 256>>>(mm1, cntm, lstm);

    // fc1: L1-tiled sparse gather + BN + LIF -> hidden masks
    fc1_tiled<<<dim3(32, 32), 1024>>>(wf1, cntm, lstm, f1b, f1s, f1sb, mh);

    // fc2 + BN + residual(xattn) -> f2o (coalesced)
    fc2k<<<NBV, 256>>>(mh, wf2, f2b, f2s, f2sb, xattn, f2o);

    // main output: transpose back to (T,B,C,V)
    tkern<<<dim3(CC / 32, VV / 32, NTB), tb32>>>(f2o, out, VV, CC);
}